// round 12
// baseline (speedup 1.0000x reference)
#include <cuda_runtime.h>

// GrassmannNN: SITE=8, DIM=16, D=32, B=8192.
// TWO kernels (was three — table+gather split removed):
//   A: 225 blocks — build 28 16x16 layer matrices M + tanh(head) vectors
//   D: 8192 warps — each row runs the 7-layer forward directly and writes
//      its 64 output floats. M is warp-redundant but L1-resident; the data
//      load + pattern ballot overlap kernel A via PDL.

__device__ float g_M[7 * 2 * 2 * 256];          // [l][bit][s][i][k], sign folded
__device__ float g_h[32];                       // tanh(head) per bit

// ---------------------------------------------------------------------------
// Kernel A: blocks 0..223 -> one (l, ig) slab of body_w each (coalesced 4KB
// load into smem, then 32 threads do the 16-length dots). Block 224 -> head.
// ---------------------------------------------------------------------------
__global__ void __launch_bounds__(256)
precompute_kernel(const float* __restrict__ emb,
                  const float* __restrict__ head_w,
                  const float* __restrict__ body_w) {
    __shared__ __align__(16) float sh[1024];
    const int b = blockIdx.x;
    const int t = threadIdx.x;

    if (b < 224) {
        const int l = b >> 5, ig = b & 31;
        reinterpret_cast<float4*>(sh)[t] =
            reinterpret_cast<const float4*>(body_w + (size_t)(l * 32 + ig) * 1024)[t];
        __syncthreads();
        if (t < 32) {
            const int bit = t >> 4, k = t & 15;
            const int s1 = ig >> 4, i = ig & 15;
            const int s = bit ? (1 - s1) : s1;
            const float* e = emb + ((l + 1) * 2 + bit) * 16;
            float acc = 0.f;
#pragma unroll
            for (int j = 0; j < 16; ++j)
                acc = fmaf(e[j], sh[(bit * 16 + j) * 32 + s * 16 + k], acc);
            if (bit == 1 && s == 0) acc = -acc;
            g_M[(((l * 2 + bit) * 2 + s) * 16 + i) * 16 + k] = acc;
        }
    } else if (t < 32) {
        const int bit = t >> 4, j = t & 15;
        const float* e = emb + bit * 16;                 // embedding[0][bit]
        float acc = 0.f;
#pragma unroll
        for (int k = 0; k < 16; ++k)
            acc = fmaf(e[k], head_w[(bit * 16 + k) * 32 + bit * 16 + j], acc);
        g_h[bit * 16 + j] = tanhf(acc);
    }
    cudaTriggerProgrammaticLaunchCompletion();
}

// ---------------------------------------------------------------------------
// Kernel D: one warp per ROW. Pattern index via ballot over lanes 0..7's
// data loads (overlaps kernel A — it's before the PDL sync). Then the
// 7-layer forward with double-buffered M coefficients, direct output write.
// ---------------------------------------------------------------------------
__global__ void __launch_bounds__(256)
forward_kernel(const int* __restrict__ data, float* __restrict__ out) {
    const int row  = (blockIdx.x * blockDim.x + threadIdx.x) >> 5;  // 0..8191
    const int lane = threadIdx.x & 31;
    const int s = lane >> 4, k = lane & 15;

    // ---- prolog (input-only; overlaps producer kernel) ----
    int bv = 0;
    if (lane < 8) bv = __ldg(data + row * 8 + lane);
    const int p = (int)(__ballot_sync(0xffffffffu, bv != 0) & 0xffu);

    cudaGridDependencySynchronize();            // wait for A's g_M / g_h

    const int bit0 = p & 1;
    float u = (s == bit0) ? g_h[bit0 * 16 + k] : 0.f;

    float m[16];
    {
        const int bit = (p >> 1) & 1;
        const float* Mp = g_M + ((0 * 2 + bit) * 2 + s) * 256 + k;
#pragma unroll
        for (int i = 0; i < 16; ++i) m[i] = Mp[i * 16];
    }
#pragma unroll
    for (int l = 0; l < 7; ++l) {
        float m2[16];
        if (l < 6) {
            const int bitn = (p >> (l + 2)) & 1;
            const float* Mn = g_M + (((l + 1) * 2 + bitn) * 2 + s) * 256 + k;
#pragma unroll
            for (int i = 0; i < 16; ++i) m2[i] = Mn[i * 16];
        }
        const int bit = (p >> (l + 1)) & 1;
        const int src = (bit ? (1 - s) : s) << 4;
        float acc = 0.f;
#pragma unroll
        for (int i = 0; i < 16; ++i)
            acc = fmaf(__shfl_sync(0xffffffffu, u, src + i), m[i], acc);
        u = tanhf(acc);
#pragma unroll
        for (int i = 0; i < 16; ++i) m[i] = m2[i];
    }

    // ---- write this row's 64 floats: live sector + structural zeros ----
    float* o = out + (size_t)row * 64;
    o[48 * s + k] = u;               // offset s*32 + s*16 + k
    o[16 + 16 * s + k] = 0.f;        // offset s*32 + (1-s)*16 + k
}

extern "C" void kernel_launch(void* const* d_in, const int* in_sizes, int n_in,
                              void* d_out, int out_size) {
    const int*   data      = (const int*)d_in[0];    // (8192, 8) int32
    const float* embedding = (const float*)d_in[1];  // (8, 2, 16)
    const float* head_w    = (const float*)d_in[2];  // (32, 32)
    const float* body_w    = (const float*)d_in[3];  // (7, 32, 32, 32)
    float* out = (float*)d_out;                      // (8192, 2, 32)

    precompute_kernel<<<225, 256>>>(embedding, head_w, body_w);

    cudaLaunchAttribute attr[1];
    attr[0].id = cudaLaunchAttributeProgrammaticStreamSerialization;
    attr[0].val.programmaticStreamSerializationAllowed = 1;

    cudaLaunchConfig_t cfg = {};
    cfg.gridDim = dim3(1024);                        // 8192 warps = 8192 rows
    cfg.blockDim = dim3(256);
    cfg.stream = 0;
    cfg.attrs = attr;
    cfg.numAttrs = 1;
    cudaLaunchKernelEx(&cfg, forward_kernel, data, (float*)d_out);
}

// round 13
// speedup vs baseline: 1.5685x; 1.5685x over previous
#include <cuda_runtime.h>

// GrassmannNN: SITE=8, DIM=16, D=32, B=8192.
// TWO kernels:
//   AB: 32 blocks as 4 clusters of 8. Each cluster builds all 28 16x16 layer
//       matrices (rank r computes slabs [r*28, r*28+28) into a per-cluster
//       global copy), cluster-barriers (HW, ~400cyc), then each block's 8
//       warps forward their 8 patterns -> 32-float live table g_T.
//   C:  131072 threads — per-row gather, zeros synthesized. PDL-chained.

__device__ float g_Mc[4 * 7168];                // per-cluster M copies
__device__ __align__(16) float g_T[256 * 32];   // live sector values only

// dynamic smem layout (floats):
//   [0, 28672)        28 slabs of body_w (4KB each)
//   [28672, 28704)    h[32]
//   [28704, 28960)    emb staging (256)
//   [28960, 29984)    head_w staging (1024)
#define SH_SLAB 0
#define SH_H    28672
#define SH_EMB  28704
#define SH_HW   28960
#define SH_FLOATS 29984

__global__ void __launch_bounds__(256)
__cluster_dims__(8, 1, 1)
build_forward_kernel(const float* __restrict__ emb,
                     const float* __restrict__ head_w,
                     const float* __restrict__ body_w) {
    extern __shared__ float sh[];
    const int t = threadIdx.x;
    const int c = blockIdx.x >> 3;              // cluster 0..3
    const int r = blockIdx.x & 7;               // rank in cluster
    float* Mc = g_Mc + c * 7168;

    // ---- phase 1: stage inputs (all loads issued up front, one sync) ----
    {
        // 28 contiguous slabs: body_w[r*28*1024 .. +28672)
        const float4* g4 = reinterpret_cast<const float4*>(body_w + (size_t)r * 28672);
        float4* s4 = reinterpret_cast<float4*>(sh + SH_SLAB);
#pragma unroll
        for (int j = 0; j < 28; ++j)
            s4[t + j * 256] = g4[t + j * 256];
        if (t < 64)
            reinterpret_cast<float4*>(sh + SH_EMB)[t] =
                reinterpret_cast<const float4*>(emb)[t];
        reinterpret_cast<float4*>(sh + SH_HW)[t] =
            reinterpret_cast<const float4*>(head_w)[t];
    }
    __syncthreads();

    // ---- head vectors (every block computes its own copy) ----
    if (t < 32) {
        const int bit = t >> 4, j = t & 15;
        const float* e = sh + SH_EMB + bit * 16;         // embedding[0][bit]
        float acc = 0.f;
#pragma unroll
        for (int k = 0; k < 16; ++k)
            acc = fmaf(e[k], sh[SH_HW + (bit * 16 + k) * 32 + bit * 16 + j], acc);
        sh[SH_H + t] = tanhf(acc);
    }

    // ---- this rank's 896 M entries: 28 slabs x 32 (bit,k) outputs ----
    for (int o = t; o < 896; o += 256) {
        const int slab = o >> 5;
        const int u = o & 31;
        const int bit = u >> 4, k = u & 15;
        const int sid = r * 28 + slab;                   // global slab 0..223
        const int l = sid >> 5, ig = sid & 31;
        const int s1 = ig >> 4, i = ig & 15;
        const int s = bit ? (1 - s1) : s1;
        const float* e = sh + SH_EMB + ((l + 1) * 2 + bit) * 16;
        const float* gs = sh + SH_SLAB + slab * 1024 + bit * 512 + s * 16 + k;
        float acc = 0.f;
#pragma unroll
        for (int j = 0; j < 16; ++j)
            acc = fmaf(e[j], gs[j * 32], acc);
        if (bit == 1 && s == 0) acc = -acc;
        Mc[(((l * 2 + bit) * 2 + s) * 16 + i) * 16 + k] = acc;
    }

    // ---- cluster barrier: all 8 ranks' M writes visible ----
    __threadfence();
    asm volatile("barrier.cluster.arrive.aligned;" ::: "memory");
    asm volatile("barrier.cluster.wait.aligned;" ::: "memory");

    // ---- phase 2: 8 pattern warps per block ----
    const int lane = t & 31;
    const int p = blockIdx.x * 8 + (t >> 5);    // 0..255
    const int s = lane >> 4, k = lane & 15;
    const int bit0 = p & 1;
    float u = (s == bit0) ? sh[SH_H + bit0 * 16 + k] : 0.f;

    float m[16];
    {
        const int bit = (p >> 1) & 1;
        const float* Mp = Mc + ((0 * 2 + bit) * 2 + s) * 256 + k;
#pragma unroll
        for (int i = 0; i < 16; ++i) m[i] = Mp[i * 16];
    }
#pragma unroll
    for (int l = 0; l < 7; ++l) {
        float m2[16];
        if (l < 6) {
            const int bitn = (p >> (l + 2)) & 1;
            const float* Mn = Mc + (((l + 1) * 2 + bitn) * 2 + s) * 256 + k;
#pragma unroll
            for (int i = 0; i < 16; ++i) m2[i] = Mn[i * 16];
        }
        const int bit = (p >> (l + 1)) & 1;
        const int src = (bit ? (1 - s) : s) << 4;
        float acc = 0.f;
#pragma unroll
        for (int i = 0; i < 16; ++i)
            acc = fmaf(__shfl_sync(0xffffffffu, u, src + i), m[i], acc);
        u = tanhf(acc);
#pragma unroll
        for (int i = 0; i < 16; ++i) m[i] = m2[i];
    }

    g_T[p * 32 + s * 16 + k] = u;               // live sector only
    cudaTriggerProgrammaticLaunchCompletion();
}

// ---------------------------------------------------------------------------
// Kernel C: gather — 16 threads per row; structurally-zero halves synthesized.
// Prolog (data load + pattern index) overlaps AB via PDL.
// ---------------------------------------------------------------------------
__global__ void __launch_bounds__(256)
gather_kernel(const int* __restrict__ data, float4* __restrict__ out) {
    const int tid = blockIdx.x * blockDim.x + threadIdx.x;  // 131072
    const int row = tid >> 4;
    const int q   = tid & 15;
    const int4* d4 = reinterpret_cast<const int4*>(data + (size_t)row * 8);
    const int4 a = __ldg(d4);
    const int4 c = __ldg(d4 + 1);
    const int p = a.x | (a.y << 1) | (a.z << 2) | (a.w << 3)
                | (c.x << 4) | (c.y << 5) | (c.z << 6) | (c.w << 7);
    const int sec = q >> 2;                      // 0:s0-live 1,2:zero 3:s1-live

    cudaGridDependencySynchronize();            // wait for AB's g_T

    float4 v = make_float4(0.f, 0.f, 0.f, 0.f);
    if (sec == 0)
        v = reinterpret_cast<const float4*>(g_T)[p * 8 + (q & 3)];
    else if (sec == 3)
        v = reinterpret_cast<const float4*>(g_T)[p * 8 + 4 + (q & 3)];
    out[tid] = v;
}

extern "C" void kernel_launch(void* const* d_in, const int* in_sizes, int n_in,
                              void* d_out, int out_size) {
    const int*   data      = (const int*)d_in[0];    // (8192, 8) int32
    const float* embedding = (const float*)d_in[1];  // (8, 2, 16)
    const float* head_w    = (const float*)d_in[2];  // (32, 32)
    const float* body_w    = (const float*)d_in[3];  // (7, 32, 32, 32)

    static int smem_set = 0;
    if (!smem_set) {
        cudaFuncSetAttribute(build_forward_kernel,
                             cudaFuncAttributeMaxDynamicSharedMemorySize,
                             SH_FLOATS * 4);
        smem_set = 1;
    }

    build_forward_kernel<<<32, 256, SH_FLOATS * 4>>>(embedding, head_w, body_w);

    cudaLaunchAttribute attr[1];
    attr[0].id = cudaLaunchAttributeProgrammaticStreamSerialization;
    attr[0].val.programmaticStreamSerializationAllowed = 1;

    cudaLaunchConfig_t cfg = {};
    cfg.gridDim = dim3(512);
    cfg.blockDim = dim3(256);
    cfg.stream = 0;
    cfg.attrs = attr;
    cfg.numAttrs = 1;
    cudaLaunchKernelEx(&cfg, gather_kernel, data, (float4*)d_out);
}